// round 5
// baseline (speedup 1.0000x reference)
#include <cuda_runtime.h>
#include <math.h>

// Problem constants
#define NUM_ENT 100000
#define BATCH  4096
#define NROWS  8192          // 2*BATCH rows of H = [h1; h2]
#define DIM    768
#define NB     64            // NROWS / 128 tile grid
#define KT     16            // k-tile depth
#define PAD    132           // 128 + 4 padding (float4-aligned, bank-conflict-free)
#define C_OFF  20.0f         // logit offset = max possible logit = 1/TAU
#define INV_TAU 20.0f

// Scratch (device globals: allocation-free per harness rules)
__device__ __align__(16) float g_H[(size_t)NROWS * DIM];   // normalized gathered rows, 25.2 MB
__device__ float g_S[NROWS];                               // per-row sum of exp(logit - 20), self excluded
__device__ float g_D[BATCH];                               // diag logits G[i, B+i]/tau

// ---------------- packed fp32x2 helpers (sm_100+) ----------------
__device__ __forceinline__ unsigned long long pk2(float x, float y) {
    unsigned long long r;
    asm("mov.b64 %0, {%1, %2};" : "=l"(r) : "f"(x), "f"(y));
    return r;
}
__device__ __forceinline__ void ffma2(unsigned long long& d, unsigned long long a,
                                      unsigned long long b) {
    asm("fma.rn.f32x2 %0, %1, %2, %0;" : "+l"(d) : "l"(a), "l"(b));
}
__device__ __forceinline__ void unpk2(float& lo, float& hi, unsigned long long v) {
    asm("mov.b64 {%0, %1}, %2;" : "=f"(lo), "=f"(hi) : "l"(v));
}

// ---------------- K1: gather + L2-normalize + zero S ----------------
// train_links is int32 on device (JAX x64 disabled downgrades jnp.int64 -> int32).
__global__ void k_normalize(const float* __restrict__ emb,
                            const int* __restrict__ links) {
    int r = blockIdx.x;  // 0..NROWS-1
    int ent = (r < BATCH) ? links[2 * r] : links[2 * (r - BATCH) + 1];
    // Defensive clamp: if dtype assumption is ever wrong, fail with rel_err,
    // not an illegal memory access.
    if (ent < 0) ent = 0;
    if (ent >= NUM_ENT) ent = NUM_ENT - 1;
    const float* src = emb + (size_t)ent * DIM;

    float ss = 0.f;
    for (int c = threadIdx.x; c < DIM; c += 256) {
        float v = src[c];
        ss += v * v;
    }
#pragma unroll
    for (int o = 16; o; o >>= 1) ss += __shfl_xor_sync(0xffffffffu, ss, o);
    __shared__ float ws[8];
    if ((threadIdx.x & 31) == 0) ws[threadIdx.x >> 5] = ss;
    __syncthreads();
    if (threadIdx.x == 0) {
        float t = 0.f;
#pragma unroll
        for (int i = 0; i < 8; i++) t += ws[i];
        ws[0] = t;
        g_S[r] = 0.f;  // must re-zero on every graph replay
    }
    __syncthreads();
    float inv = rsqrtf(ws[0]);
    float* dst = g_H + (size_t)r * DIM;
    for (int c = threadIdx.x; c < DIM; c += 256) dst[c] = src[c] * inv;
}

// ---------------- K2: triangular Gram tiles + fused exp row/col sums ----------------
// Upper-triangle 128x128 tiles (bi <= bj). Each exp value contributes to S[row]
// and, for off-diagonal tiles, also to S[col] (symmetry). Self column excluded.
__global__ __launch_bounds__(256, 2) void k_gram_lse() {
    __shared__ float As[KT][PAD];
    __shared__ float Bs[KT][PAD];
    __shared__ float colsum[128];

    // Closed-form linear id -> upper-triangular (bi, bj), bi <= bj < NB.
    // Row bi starts at idx = bi*NB - bi*(bi-1)/2.
    const float fidx = (float)blockIdx.x;
    int bi = (int)((2.0f * NB + 1.0f - sqrtf((2.0f * NB + 1.0f) * (2.0f * NB + 1.0f)
                                             - 8.0f * fidx)) * 0.5f);
    if (bi < 0) bi = 0;
    if (bi > NB - 1) bi = NB - 1;
    // guard against fp rounding at row boundaries
    while (bi > 0 && (int)blockIdx.x < bi * NB - (bi * (bi - 1)) / 2) bi--;
    while (bi < NB - 1 && (int)blockIdx.x >= (bi + 1) * NB - ((bi + 1) * bi) / 2) bi++;
    int bj = bi + ((int)blockIdx.x - (bi * NB - (bi * (bi - 1)) / 2));

    const int rowBase = bi * 128;
    const int colBase = bj * 128;
    const int tx = threadIdx.x;
    const int ty = tx >> 4;        // 0..15 -> row micro-tile
    const int txx = tx & 15;       // 0..15 -> col micro-tile

    unsigned long long acc2[8][4];  // 8 rows x 4 packed col-pairs (fp32x2)
#pragma unroll
    for (int u = 0; u < 8; u++)
#pragma unroll
        for (int v2 = 0; v2 < 4; v2++) acc2[u][v2] = 0ull;

    const float* Aptr = g_H + (size_t)rowBase * DIM;
    const float* Bptr = g_H + (size_t)colBase * DIM;

    for (int k0 = 0; k0 < DIM; k0 += KT) {
#pragma unroll
        for (int l = 0; l < 2; l++) {
            int f = tx + l * 256;          // 0..511 float4 id
            int row = f >> 2;
            int kk4 = (f & 3) * 4;
            float4 a = *(const float4*)(Aptr + (size_t)row * DIM + k0 + kk4);
            As[kk4 + 0][row] = a.x; As[kk4 + 1][row] = a.y;
            As[kk4 + 2][row] = a.z; As[kk4 + 3][row] = a.w;
            float4 b = *(const float4*)(Bptr + (size_t)row * DIM + k0 + kk4);
            Bs[kk4 + 0][row] = b.x; Bs[kk4 + 1][row] = b.y;
            Bs[kk4 + 2][row] = b.z; Bs[kk4 + 3][row] = b.w;
        }
        __syncthreads();
#pragma unroll
        for (int k = 0; k < KT; k++) {
            float4 a0 = *(const float4*)&As[k][ty * 8];
            float4 a1 = *(const float4*)&As[k][ty * 8 + 4];
            float4 b0 = *(const float4*)&Bs[k][txx * 8];
            float4 b1 = *(const float4*)&Bs[k][txx * 8 + 4];
            float ar[8] = {a0.x, a0.y, a0.z, a0.w, a1.x, a1.y, a1.z, a1.w};
            unsigned long long b2[4];
            b2[0] = pk2(b0.x, b0.y); b2[1] = pk2(b0.z, b0.w);
            b2[2] = pk2(b1.x, b1.y); b2[3] = pk2(b1.z, b1.w);
#pragma unroll
            for (int u = 0; u < 8; u++) {
                unsigned long long a2 = pk2(ar[u], ar[u]);
#pragma unroll
                for (int v2 = 0; v2 < 4; v2++) ffma2(acc2[u][v2], a2, b2[v2]);
            }
        }
        __syncthreads();
    }

    // Epilogue: scale by 1/tau, capture pair-diagonal, exp, row/col partial sums
    float prow[8], pcol[8];
#pragma unroll
    for (int u = 0; u < 8; u++) prow[u] = 0.f;
#pragma unroll
    for (int v = 0; v < 8; v++) pcol[v] = 0.f;

#pragma unroll
    for (int u = 0; u < 8; u++) {
        int rG = rowBase + ty * 8 + u;
#pragma unroll
        for (int v2 = 0; v2 < 4; v2++) {
            float glo, ghi;
            unpk2(glo, ghi, acc2[u][v2]);
#pragma unroll
            for (int h = 0; h < 2; h++) {
                int v = v2 * 2 + h;
                int cG = colBase + txx * 8 + v;
                float val = (h ? ghi : glo) * INV_TAU;
                if (cG == rG + BATCH) g_D[rG] = val;   // diag of logits_ab
                float e = (rG == cG) ? 0.f : __expf(val - C_OFF);  // exclude self (mask)
                prow[u] += e;
                pcol[v] += e;
            }
        }
    }

    // Row sums: reduce across the 16 txx lanes (xor<16 stays in each half-warp)
#pragma unroll
    for (int u = 0; u < 8; u++) {
#pragma unroll
        for (int o = 1; o < 16; o <<= 1)
            prow[u] += __shfl_xor_sync(0xffffffffu, prow[u], o);
    }
    if (txx == 0) {
#pragma unroll
        for (int u = 0; u < 8; u++) atomicAdd(&g_S[rowBase + ty * 8 + u], prow[u]);
    }

    // Col sums (only off-diagonal tiles; diag tiles already covered both orders)
    if (tx < 128) colsum[tx] = 0.f;
    __syncthreads();
    if (bi != bj) {
#pragma unroll
        for (int v = 0; v < 8; v++) atomicAdd(&colsum[txx * 8 + v], pcol[v]);
    }
    __syncthreads();
    if (bi != bj && tx < 128) atomicAdd(&g_S[colBase + tx], colsum[tx]);
}

// ---------------- K3: final loss reduction ----------------
__global__ void k_finalize(float* __restrict__ out) {
    float acc = 0.f;
    for (int i = threadIdx.x; i < BATCH; i += 256) {
        float lse_a = C_OFF + logf(g_S[i]);
        float lse_b = C_OFF + logf(g_S[BATCH + i]);
        acc += 0.5f * (lse_a + lse_b) - g_D[i];   // ALPHA = 0.5
    }
#pragma unroll
    for (int o = 16; o; o >>= 1) acc += __shfl_xor_sync(0xffffffffu, acc, o);
    __shared__ float ws[8];
    if ((threadIdx.x & 31) == 0) ws[threadIdx.x >> 5] = acc;
    __syncthreads();
    if (threadIdx.x == 0) {
        float t = 0.f;
#pragma unroll
        for (int i = 0; i < 8; i++) t += ws[i];
        out[0] = t * (1.0f / BATCH);
    }
}

extern "C" void kernel_launch(void* const* d_in, const int* in_sizes, int n_in,
                              void* d_out, int out_size) {
    const float* emb = (const float*)d_in[0];
    const int* links = (const int*)d_in[1];

    k_normalize<<<NROWS, 256>>>(emb, links);
    k_gram_lse<<<NB * (NB + 1) / 2, 256>>>();
    k_finalize<<<1, 256>>>((float*)d_out);
}

// round 8
// speedup vs baseline: 6.3756x; 6.3756x over previous
#include <cuda_runtime.h>
#include <cuda_bf16.h>
#include <cstdint>
#include <math.h>

// ---- problem constants ----
#define NUM_ENT 100000
#define BATCH   4096
#define NROWS   8192         // 2*BATCH rows of H = [h1; h2]
#define DIM     768
#define NB      64           // NROWS / 128 tile grid
#define NCHUNK  12           // DIM / 64
#define C_OFF   20.0f
#define INV_TAU 20.0f

#define SMSTRIDE 144         // bytes per SMEM row: 64 bf16 (128B) + 16B pad -> ldmatrix conflict-free

// ---- device scratch ----
__device__ __align__(16) __nv_bfloat16 g_Hb[(size_t)NROWS * DIM];  // 12.6 MB
__device__ float g_S[NROWS];
__device__ float g_D[BATCH];

__device__ __forceinline__ uint32_t smem_u32(const void* p) {
    uint32_t a;
    asm("{ .reg .u64 t; cvta.to.shared.u64 t, %1; cvt.u32.u64 %0, t; }" : "=r"(a) : "l"(p));
    return a;
}
__device__ __forceinline__ void ldsm_x4(uint32_t& r0, uint32_t& r1, uint32_t& r2, uint32_t& r3,
                                        uint32_t addr) {
    asm volatile("ldmatrix.sync.aligned.m8n8.x4.shared.b16 {%0,%1,%2,%3}, [%4];"
                 : "=r"(r0), "=r"(r1), "=r"(r2), "=r"(r3) : "r"(addr));
}
__device__ __forceinline__ void mma_bf16(float* c, const uint32_t* a, uint32_t b0, uint32_t b1) {
    asm volatile(
        "mma.sync.aligned.m16n8k16.row.col.f32.bf16.bf16.f32 "
        "{%0,%1,%2,%3}, {%4,%5,%6,%7}, {%8,%9}, {%0,%1,%2,%3};"
        : "+f"(c[0]), "+f"(c[1]), "+f"(c[2]), "+f"(c[3])
        : "r"(a[0]), "r"(a[1]), "r"(a[2]), "r"(a[3]), "r"(b0), "r"(b1));
}

// ---------------- K1: gather + L2-normalize -> bf16 H, zero S ----------------
__global__ void k_normalize(const float* __restrict__ emb,
                            const int* __restrict__ links) {
    int r = blockIdx.x;
    int ent = (r < BATCH) ? links[2 * r] : links[2 * (r - BATCH) + 1];
    if (ent < 0) ent = 0;
    if (ent >= NUM_ENT) ent = NUM_ENT - 1;
    const float* src = emb + (size_t)ent * DIM;

    float ss = 0.f;
    for (int c = threadIdx.x; c < DIM; c += 256) {
        float v = src[c];
        ss += v * v;
    }
#pragma unroll
    for (int o = 16; o; o >>= 1) ss += __shfl_xor_sync(0xffffffffu, ss, o);
    __shared__ float ws[8];
    if ((threadIdx.x & 31) == 0) ws[threadIdx.x >> 5] = ss;
    __syncthreads();
    if (threadIdx.x == 0) {
        float t = 0.f;
#pragma unroll
        for (int i = 0; i < 8; i++) t += ws[i];
        ws[0] = t;
        g_S[r] = 0.f;  // re-zero on every graph replay
    }
    __syncthreads();
    float inv = rsqrtf(ws[0]);
    __nv_bfloat16* dst = g_Hb + (size_t)r * DIM;
    for (int c = threadIdx.x; c < DIM; c += 256)
        dst[c] = __float2bfloat16(src[c] * inv);
}

// ---------------- K2: triangular 128x128 Gram tiles via mma.sync + fused LSE ----------------
__global__ void __launch_bounds__(256, 2) k_gram() {
    __shared__ __align__(16) char smA[128 * SMSTRIDE];
    __shared__ __align__(16) char smB[128 * SMSTRIDE];
    const uint32_t sbA = smem_u32(smA);
    const uint32_t sbB = smem_u32(smB);

    // Closed-form linear id -> upper-triangular (bi, bj), bi <= bj < NB (validated in R5).
    const float fidx = (float)blockIdx.x;
    int bi = (int)((2.0f * NB + 1.0f - sqrtf((2.0f * NB + 1.0f) * (2.0f * NB + 1.0f)
                                             - 8.0f * fidx)) * 0.5f);
    if (bi < 0) bi = 0;
    if (bi > NB - 1) bi = NB - 1;
    while (bi > 0 && (int)blockIdx.x < bi * NB - (bi * (bi - 1)) / 2) bi--;
    while (bi < NB - 1 && (int)blockIdx.x >= (bi + 1) * NB - ((bi + 1) * bi) / 2) bi++;
    const int bj = bi + ((int)blockIdx.x - (bi * NB - (bi * (bi - 1)) / 2));

    const int rowBase = bi * 128;
    const int colBase = bj * 128;
    const int tid = threadIdx.x, wid = tid >> 5, lid = tid & 31;
    const int wm = (wid >> 2) * 64;   // warp m-offset (0 or 64)
    const int wn = (wid & 3) * 32;    // warp n-offset (0,32,64,96)

    const char* gA = (const char*)(g_Hb + (size_t)rowBase * DIM);  // 1536 B per row
    const char* gB = (const char*)(g_Hb + (size_t)colBase * DIM);

    float c[4][4][4];
#pragma unroll
    for (int am = 0; am < 4; am++)
#pragma unroll
        for (int an = 0; an < 4; an++)
#pragma unroll
            for (int q = 0; q < 4; q++) c[am][an][q] = 0.f;

    for (int ch = 0; ch < NCHUNK; ch++) {
        __syncthreads();  // previous chunk fully consumed
        // Load A and B chunks: 128 rows x 64 bf16 (128 B) each
#pragma unroll
        for (int i = 0; i < 4; i++) {
            int idx = tid + i * 256;        // 0..1023
            int row = idx >> 3;
            int f4 = (idx & 7) * 16;
            *(float4*)(smA + row * SMSTRIDE + f4) =
                *(const float4*)(gA + (size_t)row * 1536 + ch * 128 + f4);
            *(float4*)(smB + row * SMSTRIDE + f4) =
                *(const float4*)(gB + (size_t)row * 1536 + ch * 128 + f4);
        }
        __syncthreads();

#pragma unroll
        for (int kh = 0; kh < 2; kh++) {   // two 32-wide k halves
            uint32_t bfr[4][4];
#pragma unroll
            for (int an = 0; an < 4; an++) {
                int n = wn + an * 8 + (lid & 7);
                uint32_t addr = sbB + n * SMSTRIDE + kh * 64 + ((lid >> 3) & 3) * 16;
                ldsm_x4(bfr[an][0], bfr[an][1], bfr[an][2], bfr[an][3], addr);
            }
#pragma unroll
            for (int k2 = 0; k2 < 2; k2++) {  // kstep = kh*2 + k2 (16 wide)
                uint32_t afr[4][4];
#pragma unroll
                for (int am = 0; am < 4; am++) {
                    int row = wm + am * 16 + (lid & 15);
                    uint32_t addr = sbA + row * SMSTRIDE + (kh * 2 + k2) * 32 + (lid >> 4) * 16;
                    ldsm_x4(afr[am][0], afr[am][1], afr[am][2], afr[am][3], addr);
                }
#pragma unroll
                for (int am = 0; am < 4; am++)
#pragma unroll
                    for (int an = 0; an < 4; an++)
                        mma_bf16(c[am][an], afr[am], bfr[an][k2 * 2], bfr[an][k2 * 2 + 1]);
            }
        }
    }

    // ---- Epilogue: scale, diag capture, exp (self-excluded), row & col sums ----
    float rs[8];   // row sums: [am*2 + half]
    float cs[8];   // col sums: [an*2 + subcol]
#pragma unroll
    for (int i = 0; i < 8; i++) { rs[i] = 0.f; cs[i] = 0.f; }

#pragma unroll
    for (int am = 0; am < 4; am++) {
        int rG0 = rowBase + wm + am * 16 + (lid >> 2);
#pragma unroll
        for (int an = 0; an < 4; an++) {
            int cG0 = colBase + wn + an * 8 + (lid & 3) * 2;
#pragma unroll
            for (int q = 0; q < 4; q++) {
                int rG = rG0 + (q >> 1) * 8;
                int cG = cG0 + (q & 1);
                float val = c[am][an][q] * INV_TAU;
                if (cG == rG + BATCH) g_D[rG] = val;  // diag of logits_ab
                float e = (rG == cG) ? 0.f : __expf(val - C_OFF);
                rs[am * 2 + (q >> 1)] += e;
                cs[an * 2 + (q & 1)] += e;
            }
        }
    }

    // Row reduce across the quad (lanes differing in lid&3 hold same rows)
#pragma unroll
    for (int i = 0; i < 8; i++) {
        rs[i] += __shfl_xor_sync(0xffffffffu, rs[i], 1);
        rs[i] += __shfl_xor_sync(0xffffffffu, rs[i], 2);
    }
    if ((lid & 3) == 0) {
#pragma unroll
        for (int am = 0; am < 4; am++)
#pragma unroll
            for (int h = 0; h < 2; h++)
                atomicAdd(&g_S[rowBase + wm + am * 16 + (lid >> 2) + h * 8],
                          rs[am * 2 + h]);
    }

    // Col reduce across groups (lanes differing in lid>>2 hold same cols); symmetry term
    if (bi != bj) {
#pragma unroll
        for (int i = 0; i < 8; i++) {
            cs[i] += __shfl_xor_sync(0xffffffffu, cs[i], 4);
            cs[i] += __shfl_xor_sync(0xffffffffu, cs[i], 8);
            cs[i] += __shfl_xor_sync(0xffffffffu, cs[i], 16);
        }
        if (lid < 4) {
#pragma unroll
            for (int an = 0; an < 4; an++)
#pragma unroll
                for (int s = 0; s < 2; s++)
                    atomicAdd(&g_S[colBase + wn + an * 8 + lid * 2 + s],
                              cs[an * 2 + s]);
        }
    }
}

// ---------------- K3: final loss reduction ----------------
__global__ void k_finalize(float* __restrict__ out) {
    float acc = 0.f;
    for (int i = threadIdx.x; i < BATCH; i += 256) {
        float lse_a = C_OFF + logf(g_S[i]);
        float lse_b = C_OFF + logf(g_S[BATCH + i]);
        acc += 0.5f * (lse_a + lse_b) - g_D[i];  // ALPHA = 0.5
    }
#pragma unroll
    for (int o = 16; o; o >>= 1) acc += __shfl_xor_sync(0xffffffffu, acc, o);
    __shared__ float ws[8];
    if ((threadIdx.x & 31) == 0) ws[threadIdx.x >> 5] = acc;
    __syncthreads();
    if (threadIdx.x == 0) {
        float t = 0.f;
#pragma unroll
        for (int i = 0; i < 8; i++) t += ws[i];
        out[0] = t * (1.0f / BATCH);
    }
}

extern "C" void kernel_launch(void* const* d_in, const int* in_sizes, int n_in,
                              void* d_out, int out_size) {
    const float* emb = (const float*)d_in[0];
    const int* links = (const int*)d_in[1];

    k_normalize<<<NROWS, 256>>>(emb, links);
    k_gram<<<NB * (NB + 1) / 2, 256>>>();
    k_finalize<<<1, 256>>>((float*)d_out);
}

// round 11
// speedup vs baseline: 6.9683x; 1.0930x over previous
#include <cuda_runtime.h>
#include <cuda_bf16.h>
#include <cstdint>
#include <math.h>

// ---- problem constants ----
#define NUM_ENT 100000
#define BATCH   4096
#define NROWS   8192         // 2*BATCH rows of H = [h1; h2]
#define DIM     768
#define NB      64           // NROWS / 128 tile grid
#define NCHUNK  12           // DIM / 64
#define C_OFF   20.0f
#define INV_TAU 20.0f

#define SMSTRIDE 144                 // 64 bf16 (128B) + 16B pad -> ldmatrix conflict-free
#define TILEBYTES (128 * SMSTRIDE)   // 18432 B per matrix tile
#define BUFBYTES  (2 * TILEBYTES)    // A + B per stage
#define SMEM_TOTAL (2 * BUFBYTES)    // double buffered: 73728 B

// ---- device scratch ----
__device__ __align__(16) __nv_bfloat16 g_Hb[(size_t)NROWS * DIM];  // 12.6 MB
__device__ float g_S[NROWS];
__device__ float g_D[BATCH];

__device__ __forceinline__ uint32_t smem_u32(const void* p) {
    uint32_t a;
    asm("{ .reg .u64 t; cvta.to.shared.u64 t, %1; cvt.u32.u64 %0, t; }" : "=r"(a) : "l"(p));
    return a;
}
__device__ __forceinline__ void ldsm_x4(uint32_t& r0, uint32_t& r1, uint32_t& r2, uint32_t& r3,
                                        uint32_t addr) {
    asm volatile("ldmatrix.sync.aligned.m8n8.x4.shared.b16 {%0,%1,%2,%3}, [%4];"
                 : "=r"(r0), "=r"(r1), "=r"(r2), "=r"(r3) : "r"(addr));
}
__device__ __forceinline__ void mma_bf16(float* c, const uint32_t* a, uint32_t b0, uint32_t b1) {
    asm volatile(
        "mma.sync.aligned.m16n8k16.row.col.f32.bf16.bf16.f32 "
        "{%0,%1,%2,%3}, {%4,%5,%6,%7}, {%8,%9}, {%0,%1,%2,%3};"
        : "+f"(c[0]), "+f"(c[1]), "+f"(c[2]), "+f"(c[3])
        : "r"(a[0]), "r"(a[1]), "r"(a[2]), "r"(a[3]), "r"(b0), "r"(b1));
}
__device__ __forceinline__ void cp16(uint32_t dst, const void* src) {
    asm volatile("cp.async.cg.shared.global [%0], [%1], 16;" :: "r"(dst), "l"(src));
}

// ---------------- K1: warp-per-row gather + L2-normalize -> bf16 H, zero S ----------------
__global__ void k_normalize(const float* __restrict__ emb,
                            const int* __restrict__ links) {
    const int r = (blockIdx.x << 3) | (threadIdx.x >> 5);   // global warp id = row
    const int lane = threadIdx.x & 31;
    if (threadIdx.x < 8) g_S[(blockIdx.x << 3) + threadIdx.x] = 0.f;  // re-zero each replay

    int ent = (r < BATCH) ? links[2 * r] : links[2 * (r - BATCH) + 1];
    if (ent < 0) ent = 0;
    if (ent >= NUM_ENT) ent = NUM_ENT - 1;
    const float4* src = (const float4*)(emb + (size_t)ent * DIM);  // 192 float4s

    float4 v[6];
    float ss = 0.f;
#pragma unroll
    for (int j = 0; j < 6; j++) {
        v[j] = src[lane + j * 32];
        ss += v[j].x * v[j].x + v[j].y * v[j].y + v[j].z * v[j].z + v[j].w * v[j].w;
    }
#pragma unroll
    for (int o = 16; o; o >>= 1) ss += __shfl_xor_sync(0xffffffffu, ss, o);
    const float inv = rsqrtf(ss);

    uint2* dst = (uint2*)(g_Hb + (size_t)r * DIM);  // 4 bf16 per uint2
#pragma unroll
    for (int j = 0; j < 6; j++) {
        __nv_bfloat162 lo = __floats2bfloat162_rn(v[j].x * inv, v[j].y * inv);
        __nv_bfloat162 hi = __floats2bfloat162_rn(v[j].z * inv, v[j].w * inv);
        uint2 pk;
        pk.x = *(uint32_t*)&lo;
        pk.y = *(uint32_t*)&hi;
        dst[lane + j * 32] = pk;
    }
}

// ---------------- K2: triangular 128x128 Gram tiles, cp.async pipelined mma.sync ----------------
__global__ void __launch_bounds__(256, 2) k_gram() {
    extern __shared__ __align__(16) char smem[];
    const uint32_t sb = smem_u32(smem);

    // Closed-form linear id -> upper-triangular (bi, bj), bi <= bj < NB.
    const float fidx = (float)blockIdx.x;
    int bi = (int)((2.0f * NB + 1.0f - sqrtf((2.0f * NB + 1.0f) * (2.0f * NB + 1.0f)
                                             - 8.0f * fidx)) * 0.5f);
    if (bi < 0) bi = 0;
    if (bi > NB - 1) bi = NB - 1;
    while (bi > 0 && (int)blockIdx.x < bi * NB - (bi * (bi - 1)) / 2) bi--;
    while (bi < NB - 1 && (int)blockIdx.x >= (bi + 1) * NB - ((bi + 1) * bi) / 2) bi++;
    const int bj = bi + ((int)blockIdx.x - (bi * NB - (bi * (bi - 1)) / 2));

    const int rowBase = bi * 128;
    const int colBase = bj * 128;
    const int tid = threadIdx.x, wid = tid >> 5, lid = tid & 31;
    const int wm = (wid >> 2) * 64;   // warp m-offset (0 or 64)
    const int wn = (wid & 3) * 32;    // warp n-offset (0,32,64,96)

    const char* gA = (const char*)(g_Hb + (size_t)rowBase * DIM);  // 1536 B per row
    const char* gB = (const char*)(g_Hb + (size_t)colBase * DIM);

    // per-thread load coords (4 x 16B per matrix per chunk)
    int lrow[4], lq[4];
#pragma unroll
    for (int i = 0; i < 4; i++) {
        int idx = tid + i * 256;       // 0..1023
        lrow[i] = idx >> 3;
        lq[i] = (idx & 7) * 16;
    }

    // prologue: prefetch chunk 0 into buffer 0
#pragma unroll
    for (int i = 0; i < 4; i++) {
        cp16(sb + lrow[i] * SMSTRIDE + lq[i], gA + (size_t)lrow[i] * 1536 + lq[i]);
        cp16(sb + TILEBYTES + lrow[i] * SMSTRIDE + lq[i], gB + (size_t)lrow[i] * 1536 + lq[i]);
    }
    asm volatile("cp.async.commit_group;" ::: "memory");

    float c[4][4][4];
#pragma unroll
    for (int am = 0; am < 4; am++)
#pragma unroll
        for (int an = 0; an < 4; an++)
#pragma unroll
            for (int q = 0; q < 4; q++) c[am][an][q] = 0.f;

    for (int ch = 0; ch < NCHUNK; ch++) {
        // prefetch next chunk into the other buffer
        if (ch + 1 < NCHUNK) {
            const uint32_t nb = sb + ((ch + 1) & 1) * BUFBYTES;
            const int off = (ch + 1) * 128;
#pragma unroll
            for (int i = 0; i < 4; i++) {
                cp16(nb + lrow[i] * SMSTRIDE + lq[i],
                     gA + (size_t)lrow[i] * 1536 + off + lq[i]);
                cp16(nb + TILEBYTES + lrow[i] * SMSTRIDE + lq[i],
                     gB + (size_t)lrow[i] * 1536 + off + lq[i]);
            }
            asm volatile("cp.async.commit_group;" ::: "memory");
            asm volatile("cp.async.wait_group 1;" ::: "memory");
        } else {
            asm volatile("cp.async.wait_group 0;" ::: "memory");
        }
        __syncthreads();  // chunk ch data visible to all warps

        const uint32_t sbA = sb + (ch & 1) * BUFBYTES;
        const uint32_t sbB = sbA + TILEBYTES;

#pragma unroll
        for (int kh = 0; kh < 2; kh++) {   // two 32-wide k halves
            uint32_t bfr[4][4];
#pragma unroll
            for (int an = 0; an < 4; an++) {
                int n = wn + an * 8 + (lid & 7);
                uint32_t addr = sbB + n * SMSTRIDE + kh * 64 + ((lid >> 3) & 3) * 16;
                ldsm_x4(bfr[an][0], bfr[an][1], bfr[an][2], bfr[an][3], addr);
            }
#pragma unroll
            for (int k2 = 0; k2 < 2; k2++) {  // kstep = kh*2 + k2 (16 wide)
                uint32_t afr[4][4];
#pragma unroll
                for (int am = 0; am < 4; am++) {
                    int row = wm + am * 16 + (lid & 15);
                    uint32_t addr = sbA + row * SMSTRIDE + (kh * 2 + k2) * 32 + (lid >> 4) * 16;
                    ldsm_x4(afr[am][0], afr[am][1], afr[am][2], afr[am][3], addr);
                }
#pragma unroll
                for (int am = 0; am < 4; am++)
#pragma unroll
                    for (int an = 0; an < 4; an++)
                        mma_bf16(c[am][an], afr[am], bfr[an][k2 * 2], bfr[an][k2 * 2 + 1]);
            }
        }
        __syncthreads();  // all warps done with buffer (ch&1) before it is overwritten
    }

    // ---- Epilogue: scale, diag capture, exp (self-excluded), row & col sums ----
    float rs[8];   // row sums: [am*2 + half]
    float cs[8];   // col sums: [an*2 + subcol]
#pragma unroll
    for (int i = 0; i < 8; i++) { rs[i] = 0.f; cs[i] = 0.f; }

#pragma unroll
    for (int am = 0; am < 4; am++) {
        int rG0 = rowBase + wm + am * 16 + (lid >> 2);
#pragma unroll
        for (int an = 0; an < 4; an++) {
            int cG0 = colBase + wn + an * 8 + (lid & 3) * 2;
#pragma unroll
            for (int q = 0; q < 4; q++) {
                int rG = rG0 + (q >> 1) * 8;
                int cG = cG0 + (q & 1);
                float val = c[am][an][q] * INV_TAU;
                if (cG == rG + BATCH) g_D[rG] = val;  // diag of logits_ab
                float e = (rG == cG) ? 0.f : __expf(val - C_OFF);
                rs[am * 2 + (q >> 1)] += e;
                cs[an * 2 + (q & 1)] += e;
            }
        }
    }

    // Row reduce across the quad (lanes differing in lid&3 hold same rows)
#pragma unroll
    for (int i = 0; i < 8; i++) {
        rs[i] += __shfl_xor_sync(0xffffffffu, rs[i], 1);
        rs[i] += __shfl_xor_sync(0xffffffffu, rs[i], 2);
    }
    if ((lid & 3) == 0) {
#pragma unroll
        for (int am = 0; am < 4; am++)
#pragma unroll
            for (int h = 0; h < 2; h++)
                atomicAdd(&g_S[rowBase + wm + am * 16 + (lid >> 2) + h * 8],
                          rs[am * 2 + h]);
    }

    // Col reduce across groups (lanes differing in lid>>2 hold same cols); symmetry term
    if (bi != bj) {
#pragma unroll
        for (int i = 0; i < 8; i++) {
            cs[i] += __shfl_xor_sync(0xffffffffu, cs[i], 4);
            cs[i] += __shfl_xor_sync(0xffffffffu, cs[i], 8);
            cs[i] += __shfl_xor_sync(0xffffffffu, cs[i], 16);
        }
        if (lid < 4) {
#pragma unroll
            for (int an = 0; an < 4; an++)
#pragma unroll
                for (int s = 0; s < 2; s++)
                    atomicAdd(&g_S[colBase + wn + an * 8 + lid * 2 + s],
                              cs[an * 2 + s]);
        }
    }
}

// ---------------- K3: final loss reduction ----------------
__global__ void k_finalize(float* __restrict__ out) {
    float acc = 0.f;
    for (int i = threadIdx.x; i < BATCH; i += 256) {
        float lse_a = C_OFF + logf(g_S[i]);
        float lse_b = C_OFF + logf(g_S[BATCH + i]);
        acc += 0.5f * (lse_a + lse_b) - g_D[i];  // ALPHA = 0.5
    }
#pragma unroll
    for (int o = 16; o; o >>= 1) acc += __shfl_xor_sync(0xffffffffu, acc, o);
    __shared__ float ws[8];
    if ((threadIdx.x & 31) == 0) ws[threadIdx.x >> 5] = acc;
    __syncthreads();
    if (threadIdx.x == 0) {
        float t = 0.f;
#pragma unroll
        for (int i = 0; i < 8; i++) t += ws[i];
        out[0] = t * (1.0f / BATCH);
    }
}

extern "C" void kernel_launch(void* const* d_in, const int* in_sizes, int n_in,
                              void* d_out, int out_size) {
    const float* emb = (const float*)d_in[0];
    const int* links = (const int*)d_in[1];

    cudaFuncSetAttribute(k_gram, cudaFuncAttributeMaxDynamicSharedMemorySize, SMEM_TOTAL);

    k_normalize<<<NROWS / 8, 256>>>(emb, links);
    k_gram<<<NB * (NB + 1) / 2, 256, SMEM_TOTAL>>>();
    k_finalize<<<1, 256>>>((float*)d_out);
}

// round 12
// speedup vs baseline: 7.1633x; 1.0280x over previous
#include <cuda_runtime.h>
#include <cuda_bf16.h>
#include <cstdint>
#include <math.h>

// ---- problem constants ----
#define NUM_ENT 100000
#define BATCH   4096
#define NROWS   8192         // 2*BATCH rows of H = [h1; h2]
#define DIM     768
#define NB      64           // NROWS / 128 tile grid
#define NCHUNK  12           // DIM / 64
#define C_OFF   20.0f
#define INV_TAU 20.0f

#define SMSTRIDE 144                 // 64 bf16 (128B) + 16B pad -> ldmatrix conflict-free
#define TILEBYTES (128 * SMSTRIDE)   // 18432 B per matrix tile
#define BUFBYTES  (2 * TILEBYTES)    // A + B per stage
#define SMEM_TOTAL (2 * BUFBYTES)    // double buffered: 73728 B

// ---- device scratch ----
__device__ __align__(16) __nv_bfloat16 g_Hb[(size_t)NROWS * DIM];  // 12.6 MB
__device__ float g_S[NROWS];
__device__ float g_D[BATCH];

__device__ __forceinline__ uint32_t smem_u32(const void* p) {
    uint32_t a;
    asm("{ .reg .u64 t; cvta.to.shared.u64 t, %1; cvt.u32.u64 %0, t; }" : "=r"(a) : "l"(p));
    return a;
}
__device__ __forceinline__ void ldsm_x4(uint32_t& r0, uint32_t& r1, uint32_t& r2, uint32_t& r3,
                                        uint32_t addr) {
    asm volatile("ldmatrix.sync.aligned.m8n8.x4.shared.b16 {%0,%1,%2,%3}, [%4];"
                 : "=r"(r0), "=r"(r1), "=r"(r2), "=r"(r3) : "r"(addr));
}
__device__ __forceinline__ void mma_bf16(float* c, const uint32_t* a, uint32_t b0, uint32_t b1) {
    asm volatile(
        "mma.sync.aligned.m16n8k16.row.col.f32.bf16.bf16.f32 "
        "{%0,%1,%2,%3}, {%4,%5,%6,%7}, {%8,%9}, {%0,%1,%2,%3};"
        : "+f"(c[0]), "+f"(c[1]), "+f"(c[2]), "+f"(c[3])
        : "r"(a[0]), "r"(a[1]), "r"(a[2]), "r"(a[3]), "r"(b0), "r"(b1));
}
__device__ __forceinline__ void cp16(uint32_t dst, const void* src) {
    asm volatile("cp.async.cg.shared.global [%0], [%1], 16;" :: "r"(dst), "l"(src));
}

// ---------------- K1: warp-per-row gather + L2-normalize -> bf16 H, zero S ----------------
__global__ void k_normalize(const float* __restrict__ emb,
                            const int* __restrict__ links) {
    const int r = (blockIdx.x << 2) | (threadIdx.x >> 5);   // 4 rows per 128-thread block
    const int lane = threadIdx.x & 31;
    if (threadIdx.x < 4) g_S[(blockIdx.x << 2) + threadIdx.x] = 0.f;  // re-zero each replay

    int ent = (r < BATCH) ? links[2 * r] : links[2 * (r - BATCH) + 1];
    if (ent < 0) ent = 0;
    if (ent >= NUM_ENT) ent = NUM_ENT - 1;
    const float4* src = (const float4*)(emb + (size_t)ent * DIM);  // 192 float4s

    float4 v[6];
    float ss = 0.f;
#pragma unroll
    for (int j = 0; j < 6; j++) {
        v[j] = src[lane + j * 32];
        ss += v[j].x * v[j].x + v[j].y * v[j].y + v[j].z * v[j].z + v[j].w * v[j].w;
    }
#pragma unroll
    for (int o = 16; o; o >>= 1) ss += __shfl_xor_sync(0xffffffffu, ss, o);
    const float inv = rsqrtf(ss);

    uint2* dst = (uint2*)(g_Hb + (size_t)r * DIM);  // 4 bf16 per uint2
#pragma unroll
    for (int j = 0; j < 6; j++) {
        __nv_bfloat162 lo = __floats2bfloat162_rn(v[j].x * inv, v[j].y * inv);
        __nv_bfloat162 hi = __floats2bfloat162_rn(v[j].z * inv, v[j].w * inv);
        uint2 pk;
        pk.x = *(uint32_t*)&lo;
        pk.y = *(uint32_t*)&hi;
        dst[lane + j * 32] = pk;
    }
}

// ---------------- K2: triangular 128x128 tiles, 4 warps x (64x64), cp.async pipelined ----------------
__global__ void __launch_bounds__(128, 2) k_gram() {
    extern __shared__ __align__(16) char smem[];
    const uint32_t sb = smem_u32(smem);

    // Closed-form linear id -> upper-triangular (bi, bj), bi <= bj < NB.
    const float fidx = (float)blockIdx.x;
    int bi = (int)((2.0f * NB + 1.0f - sqrtf((2.0f * NB + 1.0f) * (2.0f * NB + 1.0f)
                                             - 8.0f * fidx)) * 0.5f);
    if (bi < 0) bi = 0;
    if (bi > NB - 1) bi = NB - 1;
    while (bi > 0 && (int)blockIdx.x < bi * NB - (bi * (bi - 1)) / 2) bi--;
    while (bi < NB - 1 && (int)blockIdx.x >= (bi + 1) * NB - ((bi + 1) * bi) / 2) bi++;
    const int bj = bi + ((int)blockIdx.x - (bi * NB - (bi * (bi - 1)) / 2));

    const int rowBase = bi * 128;
    const int colBase = bj * 128;
    const int tid = threadIdx.x, wid = tid >> 5, lid = tid & 31;
    const int wm = (wid >> 1) * 64;   // warp m-offset (0 or 64)
    const int wn = (wid & 1) * 64;    // warp n-offset (0 or 64)

    const char* gA = (const char*)(g_Hb + (size_t)rowBase * DIM);  // 1536 B per row
    const char* gB = (const char*)(g_Hb + (size_t)colBase * DIM);

    // per-thread load coords (8 x 16B per matrix per chunk, 128 threads)
    int lrow[8], lq[8];
#pragma unroll
    for (int i = 0; i < 8; i++) {
        int idx = tid + i * 128;       // 0..1023
        lrow[i] = idx >> 3;
        lq[i] = (idx & 7) * 16;
    }

    // prologue: prefetch chunk 0 into buffer 0
#pragma unroll
    for (int i = 0; i < 8; i++) {
        cp16(sb + lrow[i] * SMSTRIDE + lq[i], gA + (size_t)lrow[i] * 1536 + lq[i]);
        cp16(sb + TILEBYTES + lrow[i] * SMSTRIDE + lq[i], gB + (size_t)lrow[i] * 1536 + lq[i]);
    }
    asm volatile("cp.async.commit_group;" ::: "memory");

    float c[4][8][4];   // [am 16-row][an 8-col][quad]
#pragma unroll
    for (int am = 0; am < 4; am++)
#pragma unroll
        for (int an = 0; an < 8; an++)
#pragma unroll
            for (int q = 0; q < 4; q++) c[am][an][q] = 0.f;

    for (int ch = 0; ch < NCHUNK; ch++) {
        if (ch + 1 < NCHUNK) {
            const uint32_t nb = sb + ((ch + 1) & 1) * BUFBYTES;
            const int off = (ch + 1) * 128;
#pragma unroll
            for (int i = 0; i < 8; i++) {
                cp16(nb + lrow[i] * SMSTRIDE + lq[i],
                     gA + (size_t)lrow[i] * 1536 + off + lq[i]);
                cp16(nb + TILEBYTES + lrow[i] * SMSTRIDE + lq[i],
                     gB + (size_t)lrow[i] * 1536 + off + lq[i]);
            }
            asm volatile("cp.async.commit_group;" ::: "memory");
            asm volatile("cp.async.wait_group 1;" ::: "memory");
        } else {
            asm volatile("cp.async.wait_group 0;" ::: "memory");
        }
        __syncthreads();  // chunk ch data visible

        const uint32_t sbA = sb + (ch & 1) * BUFBYTES;
        const uint32_t sbB = sbA + TILEBYTES;

#pragma unroll
        for (int kh = 0; kh < 2; kh++) {   // two 32-wide k halves
            uint32_t bfr[8][4];
#pragma unroll
            for (int an = 0; an < 8; an++) {
                int n = wn + an * 8 + (lid & 7);
                uint32_t addr = sbB + n * SMSTRIDE + kh * 64 + ((lid >> 3) & 3) * 16;
                ldsm_x4(bfr[an][0], bfr[an][1], bfr[an][2], bfr[an][3], addr);
            }
#pragma unroll
            for (int k2 = 0; k2 < 2; k2++) {  // kstep = kh*2 + k2 (16 wide)
                uint32_t afr[4][4];
#pragma unroll
                for (int am = 0; am < 4; am++) {
                    int row = wm + am * 16 + (lid & 15);
                    uint32_t addr = sbA + row * SMSTRIDE + (kh * 2 + k2) * 32 + (lid >> 4) * 16;
                    ldsm_x4(afr[am][0], afr[am][1], afr[am][2], afr[am][3], addr);
                }
#pragma unroll
                for (int am = 0; am < 4; am++)
#pragma unroll
                    for (int an = 0; an < 8; an++)
                        mma_bf16(c[am][an], afr[am], bfr[an][k2 * 2], bfr[an][k2 * 2 + 1]);
            }
        }
        __syncthreads();  // all warps done with this buffer before overwrite
    }

    // ---- Epilogue: scale, diag capture, exp (self-excluded), row & col sums ----
    float rs[8];    // row sums: [am*2 + half]
    float cs[16];   // col sums: [an*2 + subcol]
#pragma unroll
    for (int i = 0; i < 8; i++) rs[i] = 0.f;
#pragma unroll
    for (int i = 0; i < 16; i++) cs[i] = 0.f;

#pragma unroll
    for (int am = 0; am < 4; am++) {
        int rG0 = rowBase + wm + am * 16 + (lid >> 2);
#pragma unroll
        for (int an = 0; an < 8; an++) {
            int cG0 = colBase + wn + an * 8 + (lid & 3) * 2;
#pragma unroll
            for (int q = 0; q < 4; q++) {
                int rG = rG0 + (q >> 1) * 8;
                int cG = cG0 + (q & 1);
                float val = c[am][an][q] * INV_TAU;
                if (cG == rG + BATCH) g_D[rG] = val;  // diag of logits_ab
                float e = (rG == cG) ? 0.f : __expf(val - C_OFF);
                rs[am * 2 + (q >> 1)] += e;
                cs[an * 2 + (q & 1)] += e;
            }
        }
    }

    // Row reduce across the quad (lanes differing in lid&3 hold same rows)
#pragma unroll
    for (int i = 0; i < 8; i++) {
        rs[i] += __shfl_xor_sync(0xffffffffu, rs[i], 1);
        rs[i] += __shfl_xor_sync(0xffffffffu, rs[i], 2);
    }
    if ((lid & 3) == 0) {
#pragma unroll
        for (int am = 0; am < 4; am++)
#pragma unroll
            for (int h = 0; h < 2; h++)
                atomicAdd(&g_S[rowBase + wm + am * 16 + (lid >> 2) + h * 8],
                          rs[am * 2 + h]);
    }

    // Col reduce across groups (lanes differing in lid>>2 hold same cols); symmetry term
    if (bi != bj) {
#pragma unroll
        for (int i = 0; i < 16; i++) {
            cs[i] += __shfl_xor_sync(0xffffffffu, cs[i], 4);
            cs[i] += __shfl_xor_sync(0xffffffffu, cs[i], 8);
            cs[i] += __shfl_xor_sync(0xffffffffu, cs[i], 16);
        }
        if (lid < 4) {
#pragma unroll
            for (int an = 0; an < 8; an++)
#pragma unroll
                for (int s = 0; s < 2; s++)
                    atomicAdd(&g_S[colBase + wn + an * 8 + lid * 2 + s],
                              cs[an * 2 + s]);
        }
    }
}

// ---------------- K3: final loss reduction ----------------
__global__ void k_finalize(float* __restrict__ out) {
    float acc = 0.f;
    for (int i = threadIdx.x; i < BATCH; i += 256) {
        float lse_a = C_OFF + logf(g_S[i]);
        float lse_b = C_OFF + logf(g_S[BATCH + i]);
        acc += 0.5f * (lse_a + lse_b) - g_D[i];  // ALPHA = 0.5
    }
#pragma unroll
    for (int o = 16; o; o >>= 1) acc += __shfl_xor_sync(0xffffffffu, acc, o);
    __shared__ float ws[8];
    if ((threadIdx.x & 31) == 0) ws[threadIdx.x >> 5] = acc;
    __syncthreads();
    if (threadIdx.x == 0) {
        float t = 0.f;
#pragma unroll
        for (int i = 0; i < 8; i++) t += ws[i];
        out[0] = t * (1.0f / BATCH);
    }
}

extern "C" void kernel_launch(void* const* d_in, const int* in_sizes, int n_in,
                              void* d_out, int out_size) {
    const float* emb = (const float*)d_in[0];
    const int* links = (const int*)d_in[1];

    cudaFuncSetAttribute(k_gram, cudaFuncAttributeMaxDynamicSharedMemorySize, SMEM_TOTAL);

    k_normalize<<<NROWS / 4, 128>>>(emb, links);
    k_gram<<<NB * (NB + 1) / 2, 128, SMEM_TOTAL>>>();
    k_finalize<<<1, 256>>>((float*)d_out);
}